// round 1
// baseline (speedup 1.0000x reference)
#include <cuda_runtime.h>
#include <cstdint>

#define NB   8
#define NA   25200
#define NC   80
#define NTOP 1000
#define NBINS 4096
#define CAP  6144
#define NA_PAD 25216   // NA rounded up to multiple of 32

// -------------------- scratch (device globals; no allocation) --------------------
__device__ unsigned long long g_selkey[NB * NA];   // (bits(1-masked)<<32) | anchor  (ascending == conf desc, idx asc)
__device__ float              g_conf[NB * NA];     // masked conf
__device__ int                g_cls[NB * NA];
__device__ int                g_hist[NB * NBINS];
__device__ int                g_chosen[NB];
__device__ int                g_ccnt[NB];
__device__ unsigned long long g_cand[NB * CAP];
__device__ float              g_topv[NB * NTOP];
__device__ float              g_clsf[NB * NTOP];
__device__ float4             g_tb[NB * NTOP];     // original boxes of top-k (sorted order)
__device__ float4             g_ob[NB * NTOP];     // class-offset boxes
__device__ unsigned           g_maskbits[NB * NTOP * 32]; // suppression matrix rows (j>i bits)

// -------------------- kernel 0: zero hist + counters --------------------
__global__ void k_zero() {
    int i = blockIdx.x * blockDim.x + threadIdx.x;
    if (i < NB * NBINS) g_hist[i] = 0;
    if (i < NB)         g_ccnt[i] = 0;
}

// -------------------- kernel 1: conf/argmax + selkey + histogram --------------------
__global__ __launch_bounds__(256) void k_conf(const float* __restrict__ scores) {
    int gw   = blockIdx.x * 8 + (threadIdx.x >> 5);   // global anchor id (b*NA + a)
    int lane = threadIdx.x & 31;
    const float* s = scores + (size_t)gw * NC;

    // packed key: value bits (nonneg floats -> int-monotone) << 8 | (255 - class)
    // max -> largest value; tie -> smallest class index (matches jnp.argmax)
    float v0 = s[lane];
    float v1 = s[lane + 32];
    unsigned long long k0 = ((unsigned long long)__float_as_uint(v0) << 8) | (unsigned)(255 - lane);
    unsigned long long k1 = ((unsigned long long)__float_as_uint(v1) << 8) | (unsigned)(255 - (lane + 32));
    unsigned long long best = (k0 > k1) ? k0 : k1;
    if (lane < 16) {
        float v2 = s[lane + 64];
        unsigned long long k2 = ((unsigned long long)__float_as_uint(v2) << 8) | (unsigned)(255 - (lane + 64));
        if (k2 > best) best = k2;
    }
#pragma unroll
    for (int off = 16; off; off >>= 1) {
        unsigned long long o = __shfl_xor_sync(0xffffffffu, best, off);
        if (o > best) best = o;
    }
    if (lane == 0) {
        int   cls  = 255 - (int)(best & 0xFFull);
        float conf = __uint_as_float((unsigned)(best >> 8));
        float m    = (conf >= 0.5f) ? conf : -1.0f;     // masked
        float t    = 1.0f - m;                           // exact (Sterbenz) for m in [0.5,1]; 2.0 for m=-1
        unsigned tb = __float_as_uint(t);                // t>0 => sign bit 0, int-monotone
        int b = gw / NA;
        int a = gw - b * NA;
        g_selkey[gw] = ((unsigned long long)tb << 32) | (unsigned)a;
        g_conf[gw]   = m;
        g_cls[gw]    = cls;
        atomicAdd(&g_hist[b * NBINS + (tb >> 20)], 1);
    }
}

// -------------------- kernel 2: decide boundary bin (per batch) --------------------
__global__ __launch_bounds__(1024) void k_decide() {
    int b = blockIdx.x, t = threadIdx.x;
    __shared__ int part[1024];
    __shared__ int s_sel;
    int h0 = g_hist[b * NBINS + t * 4 + 0];
    int h1 = g_hist[b * NBINS + t * 4 + 1];
    int h2 = g_hist[b * NBINS + t * 4 + 2];
    int h3 = g_hist[b * NBINS + t * 4 + 3];
    int local = h0 + h1 + h2 + h3;
    part[t] = local;
    if (t == 0) s_sel = 1024;
    __syncthreads();
#pragma unroll
    for (int off = 1; off < 1024; off <<= 1) {
        int v = (t >= off) ? part[t - off] : 0;
        __syncthreads();
        part[t] += v;
        __syncthreads();
    }
    int incl = part[t];
    int excl = incl - local;
    if (excl < NTOP && incl >= NTOP) atomicMin(&s_sel, t);
    __syncthreads();
    if (t == s_sel) {
        int cum = excl;
        int bin;
        if      (cum + h0 >= NTOP)           bin = t * 4 + 0;
        else if (cum + h0 + h1 >= NTOP)      bin = t * 4 + 1;
        else if (cum + h0 + h1 + h2 >= NTOP) bin = t * 4 + 2;
        else                                 bin = t * 4 + 3;
        g_chosen[b] = bin;
    }
}

// -------------------- kernel 3: compact candidates (bins <= chosen) --------------------
__global__ __launch_bounds__(256) void k_compact() {
    int b = blockIdx.y;
    int chosen = g_chosen[b];
    int lane = threadIdx.x & 31;
    int stride = gridDim.x * blockDim.x;
    for (int i = blockIdx.x * blockDim.x + threadIdx.x; i < NA_PAD; i += stride) {
        bool p = false;
        unsigned long long key = 0;
        if (i < NA) {
            key = g_selkey[b * NA + i];
            p = ((int)(key >> 52) <= chosen);
        }
        unsigned bal = __ballot_sync(0xffffffffu, p);
        if (bal) {
            int cnt = __popc(bal);
            int leader = __ffs(bal) - 1;
            int base = 0;
            if (lane == leader) base = atomicAdd(&g_ccnt[b], cnt);
            base = __shfl_sync(0xffffffffu, base, leader);
            if (p) {
                int pos = base + __popc(bal & ((1u << lane) - 1u));
                if (pos < CAP) g_cand[b * CAP + pos] = key;
            }
        }
    }
}

// -------------------- kernel 4: exact rank selection + gather (per batch) --------------------
__global__ __launch_bounds__(1024) void k_gather(const float* __restrict__ boxes) {
    int b = blockIdx.x, t = threadIdx.x;
    __shared__ unsigned long long sk[CAP];   // 48 KB
    int m = g_ccnt[b];
    if (m > CAP) m = CAP;
    for (int i = t; i < m; i += 1024) sk[i] = g_cand[b * CAP + i];
    __syncthreads();
    const float4* bx4 = (const float4*)boxes;
    for (int e = t; e < m; e += 1024) {
        unsigned long long ke = sk[e];
        int rank = 0;
        for (int j = 0; j < m; j++) rank += (sk[j] < ke) ? 1 : 0;   // keys unique -> exact rank
        if (rank < NTOP) {
            int a  = (int)(unsigned)(ke & 0xFFFFFFFFull);
            int gi = b * NA + a;
            float v  = g_conf[gi];
            float cf = (float)g_cls[gi];
            float4 bb = bx4[gi];
            int o = b * NTOP + rank;
            g_topv[o] = v;
            g_clsf[o] = cf;
            g_tb[o]   = bb;
            float off = cf * 4096.0f;   // exact (int*pow2)
            g_ob[o]   = make_float4(bb.x + off, bb.y + off, bb.z + off, bb.w + off);
        }
    }
}

// -------------------- kernel 5: IoU suppression bit matrix --------------------
__global__ __launch_bounds__(256) void k_iou() {
    int b = blockIdx.y;
    __shared__ float4 sob[NTOP];
    for (int i = threadIdx.x; i < NTOP; i += 256) sob[i] = g_ob[b * NTOP + i];
    __syncthreads();
    int w = threadIdx.x >> 5, l = threadIdx.x & 31;
    int i = blockIdx.x * 8 + w;
    float4 bi = sob[i];
    float areai = (bi.z - bi.x) * (bi.w - bi.y);
    unsigned bits = 0;
    int j0 = l * 32;
#pragma unroll 4
    for (int jj = 0; jj < 32; jj++) {
        int j = j0 + jj;
        if (j < NTOP && j > i) {
            float4 bj = sob[j];
            float xx1 = fmaxf(bi.x, bj.x);
            float yy1 = fmaxf(bi.y, bj.y);
            float xx2 = fminf(bi.z, bj.z);
            float yy2 = fminf(bi.w, bj.w);
            float iw = xx2 - xx1; iw = fmaxf(iw, 0.0f);
            float ih = yy2 - yy1; ih = fmaxf(ih, 0.0f);
            float inter = iw * ih;
            float areaj = (bj.z - bj.x) * (bj.w - bj.y);
            float u = areai + areaj - inter + 1e-7f;
            float iou = inter / u;                 // keep division: match reference rounding
            if (iou > 0.6f) bits |= (1u << jj);
        }
    }
    g_maskbits[(b * NTOP + i) * 32 + l] = bits;
}

// -------------------- kernel 6: sequential greedy scan + output --------------------
__global__ __launch_bounds__(32) void k_nms(float* __restrict__ out) {
    int b = blockIdx.x, t = threadIdx.x;
    __shared__ float    sv[NTOP];
    __shared__ unsigned srem[32];
    for (int i = t; i < NTOP; i += 32) sv[i] = g_topv[b * NTOP + i];
    __syncwarp();
    const unsigned* mrow = g_maskbits + (size_t)b * NTOP * 32;
    unsigned removed = 0;
    unsigned cur = mrow[t];                       // row 0, my word
    for (int i = 0; i < NTOP; i++) {
        unsigned nxt = (i + 1 < NTOP) ? mrow[(i + 1) * 32 + t] : 0u;   // prefetch
        unsigned rw  = __shfl_sync(0xffffffffu, removed, i >> 5);
        bool alive = !((rw >> (i & 31)) & 1u) && (sv[i] >= 0.5f);
        if (alive) removed |= cur;
        cur = nxt;
    }
    srem[t] = removed;
    __syncwarp();
    for (int r = t; r < NTOP; r += 32) {
        bool keep = (sv[r] >= 0.5f) && !((srem[r >> 5] >> (r & 31)) & 1u);
        float fk = keep ? 1.0f : 0.0f;
        int o = b * NTOP + r;
        float4 bb = g_tb[o];
        float4 o0 = make_float4(sv[r] * fk, bb.x * fk, bb.y * fk, bb.z * fk);
        float4 o1 = make_float4(bb.w * fk, (float)b * fk, g_clsf[o] * fk, 0.0f);
        ((float4*)out)[o * 2 + 0] = o0;
        ((float4*)out)[o * 2 + 1] = o1;
    }
}

// -------------------- launch --------------------
extern "C" void kernel_launch(void* const* d_in, const int* in_sizes, int n_in,
                              void* d_out, int out_size) {
    const float* boxes  = (const float*)d_in[0];
    const float* scores = (const float*)d_in[1];
    if (n_in >= 2 && in_sizes[0] > in_sizes[1]) {   // boxes is the smaller tensor
        const float* tmp = boxes; boxes = scores; scores = tmp;
    }
    k_zero<<<(NB * NBINS + 511) / 512, 512>>>();
    k_conf<<<(NB * NA) / 8, 256>>>(scores);
    k_decide<<<NB, 1024>>>();
    k_compact<<<dim3(13, NB), 256>>>();
    k_gather<<<NB, 1024>>>(boxes);
    k_iou<<<dim3(NTOP / 8, NB), 256>>>();
    k_nms<<<NB, 32>>>((float*)d_out);
    (void)out_size;
}

// round 2
// speedup vs baseline: 1.2302x; 1.2302x over previous
#include <cuda_runtime.h>
#include <cstdint>

#define NB   8
#define NA   25200
#define NC   80
#define NTOP 1000
#define NBINS 4096
#define CAP  6144
#define NA_PAD 25216

// -------------------- scratch (device globals; no allocation) --------------------
__device__ unsigned long long g_selkey[NB * NA];
__device__ float              g_conf[NB * NA];
__device__ int                g_cls[NB * NA];
__device__ int                g_hist[NB * NBINS];
__device__ int                g_chosen[NB];
__device__ int                g_ccnt[NB];
__device__ unsigned long long g_cand[NB * CAP];
__device__ float              g_topv[NB * NTOP];
__device__ float              g_clsf[NB * NTOP];
__device__ float4             g_tb[NB * NTOP];
__device__ float4             g_ob[NB * NTOP];
__device__ unsigned           g_maskbits[NB * NTOP * 32];

// -------------------- kernel 0: zero hist + counters --------------------
__global__ void k_zero() {
    int i = blockIdx.x * blockDim.x + threadIdx.x;
    if (i < NB * NBINS) g_hist[i] = 0;
    if (i < NB)         g_ccnt[i] = 0;
}

// -------------------- kernel 1: conf/argmax via REDUX + selkey + histogram --------------------
__global__ __launch_bounds__(256) void k_conf(const float* __restrict__ scores) {
    int gw   = blockIdx.x * 8 + (threadIdx.x >> 5);
    int lane = threadIdx.x & 31;
    const float* s = scores + (size_t)gw * NC;

    float v0 = s[lane];
    float v1 = s[lane + 32];
    float v2 = (lane < 16) ? s[lane + 64] : 0.0f;
    unsigned b0 = __float_as_uint(v0);
    unsigned b1 = __float_as_uint(v1);
    unsigned b2 = __float_as_uint(v2);
    // scores are nonneg -> float compare == uint compare
    unsigned mx = b0 > b1 ? b0 : b1;
    if (b2 > mx) mx = b2;
    mx = __reduce_max_sync(0xffffffffu, mx);
    unsigned c = 255u;
    if (b0 == mx) c = (unsigned)lane;
    if (b1 == mx) c = min(c, (unsigned)(lane + 32));
    if (lane < 16 && b2 == mx) c = min(c, (unsigned)(lane + 64));
    c = __reduce_min_sync(0xffffffffu, c);   // smallest class index among maxima (jnp.argmax)

    if (lane == 0) {
        float conf = __uint_as_float(mx);
        float m    = (conf >= 0.5f) ? conf : -1.0f;
        float t    = 1.0f - m;                   // exact (Sterbenz) for m in [0.5,1]
        unsigned tb = __float_as_uint(t);
        int b = gw / NA;
        int a = gw - b * NA;
        g_selkey[gw] = ((unsigned long long)tb << 32) | (unsigned)a;
        g_conf[gw]   = m;
        g_cls[gw]    = (int)c;
        atomicAdd(&g_hist[b * NBINS + (tb >> 20)], 1);
    }
}

// -------------------- kernel 2: decide boundary bin (per batch) --------------------
__global__ __launch_bounds__(1024) void k_decide() {
    int b = blockIdx.x, t = threadIdx.x;
    __shared__ int part[1024];
    __shared__ int s_sel;
    int h0 = g_hist[b * NBINS + t * 4 + 0];
    int h1 = g_hist[b * NBINS + t * 4 + 1];
    int h2 = g_hist[b * NBINS + t * 4 + 2];
    int h3 = g_hist[b * NBINS + t * 4 + 3];
    int local = h0 + h1 + h2 + h3;
    part[t] = local;
    if (t == 0) s_sel = 1024;
    __syncthreads();
#pragma unroll
    for (int off = 1; off < 1024; off <<= 1) {
        int v = (t >= off) ? part[t - off] : 0;
        __syncthreads();
        part[t] += v;
        __syncthreads();
    }
    int incl = part[t];
    int excl = incl - local;
    if (excl < NTOP && incl >= NTOP) atomicMin(&s_sel, t);
    __syncthreads();
    if (t == s_sel) {
        int cum = excl;
        int bin;
        if      (cum + h0 >= NTOP)           bin = t * 4 + 0;
        else if (cum + h0 + h1 >= NTOP)      bin = t * 4 + 1;
        else if (cum + h0 + h1 + h2 >= NTOP) bin = t * 4 + 2;
        else                                 bin = t * 4 + 3;
        g_chosen[b] = bin;
    }
}

// -------------------- kernel 3: compact candidates (one element per thread) --------------------
__global__ __launch_bounds__(256) void k_compact() {
    int b = blockIdx.y;
    int chosen = g_chosen[b];
    int lane = threadIdx.x & 31;
    int i = blockIdx.x * 256 + threadIdx.x;
    bool p = false;
    unsigned long long key = 0;
    if (i < NA) {
        key = g_selkey[b * NA + i];
        p = ((int)(key >> 52) <= chosen);
    }
    unsigned bal = __ballot_sync(0xffffffffu, p);
    if (bal) {
        int cnt = __popc(bal);
        int leader = __ffs(bal) - 1;
        int base = 0;
        if (lane == leader) base = atomicAdd(&g_ccnt[b], cnt);
        base = __shfl_sync(0xffffffffu, base, leader);
        if (p) {
            int pos = base + __popc(bal & ((1u << lane) - 1u));
            if (pos < CAP) g_cand[b * CAP + pos] = key;
        }
    }
}

// -------------------- kernel 4: exact rank selection + gather (per batch) --------------------
__global__ __launch_bounds__(1024) void k_gather(const float* __restrict__ boxes) {
    int b = blockIdx.x, t = threadIdx.x;
    __shared__ unsigned long long sk[CAP];
    int m = g_ccnt[b];
    if (m > CAP) m = CAP;
    for (int i = t; i < m; i += 1024) sk[i] = g_cand[b * CAP + i];
    __syncthreads();
    const float4* bx4 = (const float4*)boxes;
    for (int e = t; e < m; e += 1024) {
        unsigned long long ke = sk[e];
        int rank = 0;
        for (int j = 0; j < m; j++) rank += (sk[j] < ke) ? 1 : 0;
        if (rank < NTOP) {
            int a  = (int)(unsigned)(ke & 0xFFFFFFFFull);
            int gi = b * NA + a;
            float v  = g_conf[gi];
            float cf = (float)g_cls[gi];
            float4 bb = bx4[gi];
            int o = b * NTOP + rank;
            g_topv[o] = v;
            g_clsf[o] = cf;
            g_tb[o]   = bb;
            float off = cf * 4096.0f;
            g_ob[o]   = make_float4(bb.x + off, bb.y + off, bb.z + off, bb.w + off);
        }
    }
}

// -------------------- kernel 5: IoU bit matrix (conflict-free + ballot transpose) --------------------
__global__ __launch_bounds__(256) void k_iou() {
    int b = blockIdx.y;
    __shared__ float4 sob[NTOP];
    for (int i = threadIdx.x; i < NTOP; i += 256) sob[i] = g_ob[b * NTOP + i];
    __syncthreads();
    int w = threadIdx.x >> 5, l = threadIdx.x & 31;
    int i = blockIdx.x * 8 + w;
    float4 bi = sob[i];
    float areai = (bi.z - bi.x) * (bi.w - bi.y);
    unsigned mybits = 0;
#pragma unroll 4
    for (int jj = 0; jj < 32; jj++) {
        int j = jj * 32 + l;                       // consecutive lanes -> conflict-free LDS
        bool sup = false;
        if (j < NTOP && j > i) {
            float4 bj = sob[j];
            float xx1 = fmaxf(bi.x, bj.x);
            float yy1 = fmaxf(bi.y, bj.y);
            float xx2 = fminf(bi.z, bj.z);
            float yy2 = fminf(bi.w, bj.w);
            float iw = fmaxf(xx2 - xx1, 0.0f);
            float ih = fmaxf(yy2 - yy1, 0.0f);
            float inter = iw * ih;
            float areaj = (bj.z - bj.x) * (bj.w - bj.y);
            float u = areai + areaj - inter + 1e-7f;
            sup = (inter / u) > 0.6f;              // keep division: match reference rounding
        }
        unsigned word = __ballot_sync(0xffffffffu, sup);
        if (l == jj) mybits = word;                // transpose via ballot
    }
    g_maskbits[(b * NTOP + i) * 32 + l] = mybits;
}

// -------------------- kernel 6: greedy scan from SHARED (group-scan) + output --------------------
// dynamic smem layout (words):
//   smask : 1024 rows * 33 words (row-padded, conflict-free)   [0 .. 33792)
//   svalid: 32                                                  [33792 .. 33824)
//   ssv   : 1024 floats                                         [33824 .. 34848)
//   srem  : 32                                                   [34848 .. 34880)
#define NMS_SMEM_WORDS 34880
__global__ __launch_bounds__(1024) void k_nms(float* __restrict__ out) {
    extern __shared__ unsigned sh[];
    unsigned* smask  = sh;
    unsigned* svalid = sh + 33792;
    float*    ssv    = (float*)(sh + 33824);
    unsigned* srem   = sh + 34848;

    int b = blockIdx.x, t = threadIdx.x;

    // stage mask matrix: 8000 uint4 loads, store as padded rows
    const uint4* src4 = (const uint4*)(g_maskbits + (size_t)b * NTOP * 32);
    for (int k = t; k < NTOP * 8; k += 1024) {
        uint4 q = src4[k];
        int row = k >> 3, wq = (k & 7) << 2;
        unsigned* dst = smask + row * 33 + wq;
        dst[0] = q.x; dst[1] = q.y; dst[2] = q.z; dst[3] = q.w;
    }
    // stage scores + validity words
    {
        float v = (t < NTOP) ? g_topv[b * NTOP + t] : -1.0f;
        ssv[t] = v;
        unsigned wd = __ballot_sync(0xffffffffu, v >= 0.5f);
        if ((t & 31) == 0) svalid[t >> 5] = wd;
    }
    __syncthreads();

    // warp 0: greedy scan, 32 rows per group
    if (t < 32) {
        int l = t;
        unsigned removed_l = 0;
        for (int g = 0; g < 32; g++) {
            unsigned rg = __shfl_sync(0xffffffffu, removed_l, g);  // incoming removed word g
            unsigned vg = svalid[g];
            unsigned alivemask = 0;
            if (l == 0) {
                unsigned dw[32];
#pragma unroll
                for (int ii = 0; ii < 32; ii++)
                    dw[ii] = smask[(g * 32 + ii) * 33 + g];        // diagonal block, single lane: no conflict
#pragma unroll
                for (int ii = 0; ii < 32; ii++) {
                    if (((vg >> ii) & 1u) && !((rg >> ii) & 1u)) { // alive: valid & not removed
                        alivemask |= (1u << ii);
                        rg |= dw[ii];                              // in-register within-group suppression
                    }
                }
            }
            alivemask = __shfl_sync(0xffffffffu, alivemask, 0);
            unsigned am = alivemask;
            int base = (g * 32) * 33 + l;
            while (am) {                                           // apply alive rows to all 32 words
                int ii = __ffs(am) - 1; am &= am - 1;
                removed_l |= smask[base + ii * 33];
            }
        }
        srem[l] = removed_l;
    }
    __syncthreads();

    // output: one row per thread
    if (t < NTOP) {
        bool keep = (ssv[t] >= 0.5f) && !((srem[t >> 5] >> (t & 31)) & 1u);
        float fk = keep ? 1.0f : 0.0f;
        int o = b * NTOP + t;
        float4 bb = g_tb[o];
        float4 o0 = make_float4(ssv[t] * fk, bb.x * fk, bb.y * fk, bb.z * fk);
        float4 o1 = make_float4(bb.w * fk, (float)b * fk, g_clsf[o] * fk, 0.0f);
        ((float4*)out)[o * 2 + 0] = o0;
        ((float4*)out)[o * 2 + 1] = o1;
    }
}

// -------------------- launch --------------------
extern "C" void kernel_launch(void* const* d_in, const int* in_sizes, int n_in,
                              void* d_out, int out_size) {
    const float* boxes  = (const float*)d_in[0];
    const float* scores = (const float*)d_in[1];
    if (n_in >= 2 && in_sizes[0] > in_sizes[1]) {
        const float* tmp = boxes; boxes = scores; scores = tmp;
    }
    cudaFuncSetAttribute(k_nms, cudaFuncAttributeMaxDynamicSharedMemorySize,
                         NMS_SMEM_WORDS * 4);
    k_zero<<<(NB * NBINS + 511) / 512, 512>>>();
    k_conf<<<(NB * NA) / 8, 256>>>(scores);
    k_decide<<<NB, 1024>>>();
    k_compact<<<dim3((NA_PAD + 255) / 256, NB), 256>>>();
    k_gather<<<NB, 1024>>>(boxes);
    k_iou<<<dim3(NTOP / 8, NB), 256>>>();
    k_nms<<<NB, 1024, NMS_SMEM_WORDS * 4>>>((float*)d_out);
    (void)out_size;
}

// round 3
// speedup vs baseline: 1.6548x; 1.3452x over previous
#include <cuda_runtime.h>
#include <cstdint>

#define NB   8
#define NA   25200
#define NC   80
#define NTOP 1000
#define NBINS 4096
#define CAP  6144

// -------------------- scratch (device globals; no allocation) --------------------
__device__ unsigned long long g_selkey[NB * NA];   // (bits(1-masked)<<32) | (anchor<<7) | cls
__device__ int                g_hist[NB * NBINS];  // zeroed initially; k_mega re-zeroes for next replay
__device__ float              g_topv[NB * NTOP];
__device__ float              g_clsf[NB * NTOP];
__device__ float4             g_tb[NB * NTOP];
__device__ float4             g_ob[NB * NTOP];
__device__ unsigned           g_maskbits[NB * NTOP * 32];

// -------------------- kernel 1: conf/argmax (1 LDG.128/lane + REDUX) + key + histogram --------------------
__global__ __launch_bounds__(256) void k_conf(const float* __restrict__ scores) {
    int gw   = blockIdx.x * 8 + (threadIdx.x >> 5);   // b*NA + a
    int lane = threadIdx.x & 31;
    const float4* s4 = (const float4*)(scores + (size_t)gw * NC);

    unsigned b0 = 0, b1 = 0, b2 = 0, b3 = 0;
    if (lane < 20) {
        float4 v = s4[lane];
        b0 = __float_as_uint(v.x); b1 = __float_as_uint(v.y);
        b2 = __float_as_uint(v.z); b3 = __float_as_uint(v.w);
    }
    // scores nonneg -> float order == uint order
    unsigned mx = b0 > b1 ? b0 : b1;
    unsigned m2 = b2 > b3 ? b2 : b3;
    if (m2 > mx) mx = m2;
    unsigned wmx = __reduce_max_sync(0xffffffffu, mx);
    unsigned cand = 0xFFu;
    if (b3 == wmx) cand = 4u * lane + 3u;
    if (b2 == wmx) cand = 4u * lane + 2u;
    if (b1 == wmx) cand = 4u * lane + 1u;
    if (b0 == wmx) cand = 4u * lane + 0u;
    cand = __reduce_min_sync(0xffffffffu, cand);   // smallest class among maxima (jnp.argmax)

    if (lane == 0) {
        float conf = __uint_as_float(wmx);
        float m    = (conf >= 0.5f) ? conf : -1.0f;
        float t    = 1.0f - m;                     // exact (Sterbenz) for m in [0.5,1]; 2.0 for -1
        unsigned tb = __float_as_uint(t);
        int b = gw / NA;
        int a = gw - b * NA;
        g_selkey[gw] = ((unsigned long long)tb << 32) | ((unsigned)(a << 7)) | cand;
        atomicAdd(&g_hist[b * NBINS + (tb >> 20)], 1);
    }
}

// -------------------- kernel 2: mega (decide + bin-grouped compact + O(bin^2) rank + gather) --------------------
// dyn smem (words): cand[CAP ull]=12288w | pre[4096] | cnt[4096] | part[1024] | 4 scalars
#define MEGA_W_CAND 0
#define MEGA_W_PRE  12288
#define MEGA_W_CNT  16384
#define MEGA_W_PART 20480
#define MEGA_W_SCAL 21504
#define MEGA_SMEM_WORDS 21508
__global__ __launch_bounds__(1024) void k_mega(const float* __restrict__ boxes) {
    extern __shared__ unsigned shm[];
    unsigned long long* cand = (unsigned long long*)(shm + MEGA_W_CAND);
    int* pre  = (int*)(shm + MEGA_W_PRE);
    int* cnt  = (int*)(shm + MEGA_W_CNT);
    int* part = (int*)(shm + MEGA_W_PART);
    int* scal = (int*)(shm + MEGA_W_SCAL);   // [0]=s_sel [1]=chosen [2]=m

    int b = blockIdx.x, t = threadIdx.x;

    // load hist slice (4 bins/thread) and zero it for the next replay
    int hb = b * NBINS + t * 4;
    int h0 = g_hist[hb + 0], h1 = g_hist[hb + 1], h2 = g_hist[hb + 2], h3 = g_hist[hb + 3];
    g_hist[hb + 0] = 0; g_hist[hb + 1] = 0; g_hist[hb + 2] = 0; g_hist[hb + 3] = 0;
    int local = h0 + h1 + h2 + h3;
    part[t] = local;
    if (t == 0) scal[0] = 1024;
    __syncthreads();
#pragma unroll
    for (int off = 1; off < 1024; off <<= 1) {
        int v = (t >= off) ? part[t - off] : 0;
        __syncthreads();
        part[t] += v;
        __syncthreads();
    }
    int incl = part[t];
    int excl = incl - local;
    pre[t * 4 + 0] = excl;
    pre[t * 4 + 1] = excl + h0;
    pre[t * 4 + 2] = excl + h0 + h1;
    pre[t * 4 + 3] = excl + h0 + h1 + h2;
    cnt[t * 4 + 0] = 0; cnt[t * 4 + 1] = 0; cnt[t * 4 + 2] = 0; cnt[t * 4 + 3] = 0;
    if (excl < NTOP && incl >= NTOP) atomicMin(&scal[0], t);
    __syncthreads();
    if (t == scal[0]) {
        int bin, mm;
        if      (excl + h0 >= NTOP)                { bin = t * 4 + 0; mm = excl + h0; }
        else if (excl + h0 + h1 >= NTOP)           { bin = t * 4 + 1; mm = excl + h0 + h1; }
        else if (excl + h0 + h1 + h2 >= NTOP)      { bin = t * 4 + 2; mm = excl + h0 + h1 + h2; }
        else                                       { bin = t * 4 + 3; mm = excl + local; }
        scal[1] = bin; scal[2] = mm;
    }
    __syncthreads();
    int chosen = scal[1];
    int m = scal[2]; if (m > CAP) m = CAP;

    // bin-grouped compaction
    for (int i = t; i < NA; i += 1024) {
        unsigned long long key = g_selkey[b * NA + i];
        int bin = (int)(key >> 52);
        if (bin <= chosen) {
            int pos = pre[bin] + atomicAdd(&cnt[bin], 1);
            if (pos < CAP) cand[pos] = key;
        }
    }
    __syncthreads();

    // rank within own bin only, then gather
    const float4* bx4 = (const float4*)boxes;
    for (int e = t; e < m; e += 1024) {
        unsigned long long ke = cand[e];
        int bin = (int)(ke >> 52);
        int start = pre[bin];
        int end   = start + cnt[bin]; if (end > m) end = m;
        int rank  = start;
        for (int j = start; j < end; j++) rank += (cand[j] < ke) ? 1 : 0;
        if (rank < NTOP) {
            int a   = (int)((unsigned)(ke & 0xFFFFFFFFull) >> 7);
            int cls = (int)(ke & 127ull);
            float tt = __uint_as_float((unsigned)(ke >> 32));
            float v  = 1.0f - tt;                // bit-exact reconstruction of masked conf
            float cf = (float)cls;
            float4 bb = bx4[b * NA + a];
            int o = b * NTOP + rank;
            g_topv[o] = v;
            g_clsf[o] = cf;
            g_tb[o]   = bb;
            float off = cf * 4096.0f;
            g_ob[o]   = make_float4(bb.x + off, bb.y + off, bb.z + off, bb.w + off);
        }
    }
}

// -------------------- kernel 3: IoU bit matrix (conflict-free + ballot transpose) --------------------
__global__ __launch_bounds__(256) void k_iou() {
    int b = blockIdx.y;
    __shared__ float4 sob[NTOP];
    for (int i = threadIdx.x; i < NTOP; i += 256) sob[i] = g_ob[b * NTOP + i];
    __syncthreads();
    int w = threadIdx.x >> 5, l = threadIdx.x & 31;
    int i = blockIdx.x * 8 + w;
    float4 bi = sob[i];
    float areai = (bi.z - bi.x) * (bi.w - bi.y);
    unsigned mybits = 0;
#pragma unroll 4
    for (int jj = 0; jj < 32; jj++) {
        int j = jj * 32 + l;                       // consecutive lanes -> conflict-free LDS
        bool sup = false;
        if (j < NTOP && j > i) {
            float4 bj = sob[j];
            float xx1 = fmaxf(bi.x, bj.x);
            float yy1 = fmaxf(bi.y, bj.y);
            float xx2 = fminf(bi.z, bj.z);
            float yy2 = fminf(bi.w, bj.w);
            float iw = fmaxf(xx2 - xx1, 0.0f);
            float ih = fmaxf(yy2 - yy1, 0.0f);
            float inter = iw * ih;
            float areaj = (bj.z - bj.x) * (bj.w - bj.y);
            float u = areai + areaj - inter + 1e-7f;
            sup = (inter / u) > 0.6f;              // keep division: match reference rounding
        }
        unsigned word = __ballot_sync(0xffffffffu, sup);
        if (l == jj) mybits = word;
    }
    g_maskbits[(b * NTOP + i) * 32 + l] = mybits;
}

// -------------------- kernel 4: greedy scan from SHARED (group-scan) + output --------------------
// dyn smem (words): smask 1024*33 | svalid 32 | ssv 1024 | srem 32
#define NMS_SMEM_WORDS 34880
__global__ __launch_bounds__(1024) void k_nms(float* __restrict__ out) {
    extern __shared__ unsigned sh[];
    unsigned* smask  = sh;
    unsigned* svalid = sh + 33792;
    float*    ssv    = (float*)(sh + 33824);
    unsigned* srem   = sh + 34848;

    int b = blockIdx.x, t = threadIdx.x;

    const uint4* src4 = (const uint4*)(g_maskbits + (size_t)b * NTOP * 32);
    for (int k = t; k < NTOP * 8; k += 1024) {
        uint4 q = src4[k];
        int row = k >> 3, wq = (k & 7) << 2;
        unsigned* dst = smask + row * 33 + wq;
        dst[0] = q.x; dst[1] = q.y; dst[2] = q.z; dst[3] = q.w;
    }
    {
        float v = (t < NTOP) ? g_topv[b * NTOP + t] : -1.0f;
        ssv[t] = v;
        unsigned wd = __ballot_sync(0xffffffffu, v >= 0.5f);
        if ((t & 31) == 0) svalid[t >> 5] = wd;
    }
    __syncthreads();

    if (t < 32) {
        int l = t;
        unsigned removed_l = 0;
        for (int g = 0; g < 32; g++) {
            unsigned rg = __shfl_sync(0xffffffffu, removed_l, g);
            unsigned vg = svalid[g];
            unsigned alivemask = 0;
            if (l == 0) {
                unsigned dw[32];
#pragma unroll
                for (int ii = 0; ii < 32; ii++)
                    dw[ii] = smask[(g * 32 + ii) * 33 + g];
#pragma unroll
                for (int ii = 0; ii < 32; ii++) {
                    if (((vg >> ii) & 1u) && !((rg >> ii) & 1u)) {
                        alivemask |= (1u << ii);
                        rg |= dw[ii];
                    }
                }
            }
            alivemask = __shfl_sync(0xffffffffu, alivemask, 0);
            unsigned am = alivemask;
            int base = (g * 32) * 33 + l;
            while (am) {
                int ii = __ffs(am) - 1; am &= am - 1;
                removed_l |= smask[base + ii * 33];
            }
        }
        srem[l] = removed_l;
    }
    __syncthreads();

    if (t < NTOP) {
        bool keep = (ssv[t] >= 0.5f) && !((srem[t >> 5] >> (t & 31)) & 1u);
        float fk = keep ? 1.0f : 0.0f;
        int o = b * NTOP + t;
        float4 bb = g_tb[o];
        float4 o0 = make_float4(ssv[t] * fk, bb.x * fk, bb.y * fk, bb.z * fk);
        float4 o1 = make_float4(bb.w * fk, (float)b * fk, g_clsf[o] * fk, 0.0f);
        ((float4*)out)[o * 2 + 0] = o0;
        ((float4*)out)[o * 2 + 1] = o1;
    }
}

// -------------------- launch --------------------
extern "C" void kernel_launch(void* const* d_in, const int* in_sizes, int n_in,
                              void* d_out, int out_size) {
    const float* boxes  = (const float*)d_in[0];
    const float* scores = (const float*)d_in[1];
    if (n_in >= 2 && in_sizes[0] > in_sizes[1]) {
        const float* tmp = boxes; boxes = scores; scores = tmp;
    }
    cudaFuncSetAttribute(k_mega, cudaFuncAttributeMaxDynamicSharedMemorySize,
                         MEGA_SMEM_WORDS * 4);
    cudaFuncSetAttribute(k_nms, cudaFuncAttributeMaxDynamicSharedMemorySize,
                         NMS_SMEM_WORDS * 4);
    k_conf<<<(NB * NA) / 8, 256>>>(scores);
    k_mega<<<NB, 1024, MEGA_SMEM_WORDS * 4>>>(boxes);
    k_iou<<<dim3(NTOP / 8, NB), 256>>>();
    k_nms<<<NB, 1024, NMS_SMEM_WORDS * 4>>>((float*)d_out);
    (void)out_size;
}

// round 4
// speedup vs baseline: 3.0730x; 1.8570x over previous
#include <cuda_runtime.h>
#include <cstdint>

#define NB   8
#define NA   25200
#define NC   80
#define NTOP 1000
#define NBINS 4096
#define CAP  6144

// -------------------- scratch (device globals; no allocation) --------------------
__device__ unsigned long long g_selkey[NB * NA];   // (bits(1-masked)<<32) | (anchor<<7) | cls
__device__ int                g_hist[NB * NBINS];  // zeroed initially; k_mega re-zeroes each replay
__device__ float              g_topv[NB * NTOP];
__device__ float              g_clsf[NB * NTOP];
__device__ float4             g_tb[NB * NTOP];
__device__ float4             g_ob[NB * NTOP];
__device__ unsigned           g_maskbits[NB * NTOP * 32];
__device__ unsigned           g_rowflag[NB * 32];  // bit i: row i has >=1 suppression bit

// -------------------- kernel 1: conf/argmax (1 LDG.128/lane + REDUX) + key + histogram --------------------
__global__ __launch_bounds__(256) void k_conf(const float* __restrict__ scores) {
    int gw   = blockIdx.x * 8 + (threadIdx.x >> 5);   // b*NA + a
    int lane = threadIdx.x & 31;
    const float4* s4 = (const float4*)(scores + (size_t)gw * NC);

    unsigned b0 = 0, b1 = 0, b2 = 0, b3 = 0;
    if (lane < 20) {
        float4 v = s4[lane];
        b0 = __float_as_uint(v.x); b1 = __float_as_uint(v.y);
        b2 = __float_as_uint(v.z); b3 = __float_as_uint(v.w);
    }
    unsigned mx = b0 > b1 ? b0 : b1;
    unsigned m2 = b2 > b3 ? b2 : b3;
    if (m2 > mx) mx = m2;
    unsigned wmx = __reduce_max_sync(0xffffffffu, mx);
    unsigned cand = 0xFFu;
    if (b3 == wmx) cand = 4u * lane + 3u;
    if (b2 == wmx) cand = 4u * lane + 2u;
    if (b1 == wmx) cand = 4u * lane + 1u;
    if (b0 == wmx) cand = 4u * lane + 0u;
    cand = __reduce_min_sync(0xffffffffu, cand);   // smallest class among maxima (jnp.argmax)

    if (lane == 0) {
        float conf = __uint_as_float(wmx);
        float m    = (conf >= 0.5f) ? conf : -1.0f;
        float t    = 1.0f - m;                     // exact (Sterbenz) for m in [0.5,1]
        unsigned tb = __float_as_uint(t);
        int b = gw / NA;
        int a = gw - b * NA;
        g_selkey[gw] = ((unsigned long long)tb << 32) | ((unsigned)(a << 7)) | cand;
        atomicAdd(&g_hist[b * NBINS + (tb >> 20)], 1);
    }
}

// -------------------- kernel 2: mega (decide + bin-grouped compact + per-bin rank + gather) --------------------
// dyn smem (words): cand[CAP ull]=12288w | pre[4096] | cnt[4096] | wsum[32] | 4 scalars
#define MEGA_W_CAND 0
#define MEGA_W_PRE  12288
#define MEGA_W_CNT  16384
#define MEGA_W_WSUM 20480
#define MEGA_W_SCAL 20512
#define MEGA_SMEM_WORDS 20516
__global__ __launch_bounds__(1024) void k_mega(const float* __restrict__ boxes) {
    extern __shared__ unsigned shm[];
    unsigned long long* cand = (unsigned long long*)(shm + MEGA_W_CAND);
    int* pre  = (int*)(shm + MEGA_W_PRE);
    int* cnt  = (int*)(shm + MEGA_W_CNT);
    int* wsum = (int*)(shm + MEGA_W_WSUM);
    int* scal = (int*)(shm + MEGA_W_SCAL);   // [0]=s_sel [1]=chosen [2]=m

    int b = blockIdx.x, t = threadIdx.x;
    int lane = t & 31, wid = t >> 5;

    // zero rowflag for k_iou (this replay)
    if (t < 32) g_rowflag[b * 32 + t] = 0;

    // load hist slice (4 bins/thread) and zero it for the next replay
    int hb = b * NBINS + t * 4;
    int h0 = g_hist[hb + 0], h1 = g_hist[hb + 1], h2 = g_hist[hb + 2], h3 = g_hist[hb + 3];
    g_hist[hb + 0] = 0; g_hist[hb + 1] = 0; g_hist[hb + 2] = 0; g_hist[hb + 3] = 0;
    int local = h0 + h1 + h2 + h3;

    // block scan: warp shfl scan + cross-warp scan (2 barriers)
    int v = local;
#pragma unroll
    for (int off = 1; off < 32; off <<= 1) {
        int n = __shfl_up_sync(0xffffffffu, v, off);
        if (lane >= off) v += n;
    }
    if (lane == 31) wsum[wid] = v;
    if (t == 0) scal[0] = 1024;
    __syncthreads();
    if (t < 32) {
        int s = wsum[t];
        int is = s;
#pragma unroll
        for (int off = 1; off < 32; off <<= 1) {
            int n = __shfl_up_sync(0xffffffffu, is, off);
            if (t >= off) is += n;
        }
        wsum[t] = is - s;   // exclusive base
    }
    __syncthreads();
    int incl = v + wsum[wid];
    int excl = incl - local;
    pre[t * 4 + 0] = excl;
    pre[t * 4 + 1] = excl + h0;
    pre[t * 4 + 2] = excl + h0 + h1;
    pre[t * 4 + 3] = excl + h0 + h1 + h2;
    cnt[t * 4 + 0] = 0; cnt[t * 4 + 1] = 0; cnt[t * 4 + 2] = 0; cnt[t * 4 + 3] = 0;
    if (excl < NTOP && incl >= NTOP) atomicMin(&scal[0], t);
    __syncthreads();
    if (t == scal[0]) {
        int bin, mm;
        if      (excl + h0 >= NTOP)           { bin = t * 4 + 0; mm = excl + h0; }
        else if (excl + h0 + h1 >= NTOP)      { bin = t * 4 + 1; mm = excl + h0 + h1; }
        else if (excl + h0 + h1 + h2 >= NTOP) { bin = t * 4 + 2; mm = excl + h0 + h1 + h2; }
        else                                  { bin = t * 4 + 3; mm = excl + local; }
        scal[1] = bin; scal[2] = mm;
    }
    __syncthreads();
    int chosen = scal[1];
    int m = scal[2]; if (m > CAP) m = CAP;

    // bin-grouped compaction
    for (int i = t; i < NA; i += 1024) {
        unsigned long long key = g_selkey[b * NA + i];
        int bin = (int)(key >> 52);
        if (bin <= chosen) {
            int pos = pre[bin] + atomicAdd(&cnt[bin], 1);
            if (pos < CAP) cand[pos] = key;
        }
    }
    __syncthreads();

    // rank within own bin only, then gather
    const float4* bx4 = (const float4*)boxes;
    for (int e = t; e < m; e += 1024) {
        unsigned long long ke = cand[e];
        int bin = (int)(ke >> 52);
        int start = pre[bin];
        int end   = start + cnt[bin]; if (end > m) end = m;
        int rank  = start;
        for (int j = start; j < end; j++) rank += (cand[j] < ke) ? 1 : 0;
        if (rank < NTOP) {
            int a   = (int)((unsigned)(ke & 0xFFFFFFFFull) >> 7);
            int cls = (int)(ke & 127ull);
            float tt = __uint_as_float((unsigned)(ke >> 32));
            float vv = 1.0f - tt;                // bit-exact reconstruction of masked conf
            float cf = (float)cls;
            float4 bb = bx4[b * NA + a];
            int o = b * NTOP + rank;
            g_topv[o] = vv;
            g_clsf[o] = cf;
            g_tb[o]   = bb;
            float off = cf * 4096.0f;
            g_ob[o]   = make_float4(bb.x + off, bb.y + off, bb.z + off, bb.w + off);
        }
    }
}

// -------------------- kernel 3: IoU bit matrix + row flags --------------------
__global__ __launch_bounds__(256) void k_iou() {
    int b = blockIdx.y;
    __shared__ float4 sob[NTOP];
    for (int i = threadIdx.x; i < NTOP; i += 256) sob[i] = g_ob[b * NTOP + i];
    __syncthreads();
    int w = threadIdx.x >> 5, l = threadIdx.x & 31;
    int i = blockIdx.x * 8 + w;
    float4 bi = sob[i];
    float areai = (bi.z - bi.x) * (bi.w - bi.y);
    unsigned mybits = 0;
#pragma unroll 4
    for (int jj = 0; jj < 32; jj++) {
        int j = jj * 32 + l;                       // consecutive lanes -> conflict-free LDS
        bool sup = false;
        if (j < NTOP && j > i) {
            float4 bj = sob[j];
            float xx1 = fmaxf(bi.x, bj.x);
            float yy1 = fmaxf(bi.y, bj.y);
            float xx2 = fminf(bi.z, bj.z);
            float yy2 = fminf(bi.w, bj.w);
            float iw = fmaxf(xx2 - xx1, 0.0f);
            float ih = fmaxf(yy2 - yy1, 0.0f);
            float inter = iw * ih;
            float areaj = (bj.z - bj.x) * (bj.w - bj.y);
            float u = areai + areaj - inter + 1e-7f;
            sup = (inter / u) > 0.6f;              // keep division: match reference rounding
        }
        unsigned word = __ballot_sync(0xffffffffu, sup);
        if (l == jj) mybits = word;
    }
    g_maskbits[(b * NTOP + i) * 32 + l] = mybits;
    unsigned nz = __ballot_sync(0xffffffffu, mybits != 0);
    if (l == 0 && nz) atomicOr(&g_rowflag[b * 32 + (i >> 5)], 1u << (i & 31));
}

// -------------------- kernel 4: sparse greedy scan + output --------------------
// dyn smem (words): sst 1000*33 | slist 1024 | svalid 32 | ssv 1024 | srem 32 | scount 4
#define NMS_W_SST   0
#define NMS_W_LIST  33000
#define NMS_W_VAL   34024
#define NMS_W_SSV   34056
#define NMS_W_REM   35080
#define NMS_W_CNT   35112
#define NMS_SMEM_WORDS 35116
__global__ __launch_bounds__(1024) void k_nms(float* __restrict__ out) {
    extern __shared__ unsigned sh[];
    unsigned* sst    = sh + NMS_W_SST;
    int*      slist  = (int*)(sh + NMS_W_LIST);
    unsigned* svalid = sh + NMS_W_VAL;
    float*    ssv    = (float*)(sh + NMS_W_SSV);
    unsigned* srem   = sh + NMS_W_REM;
    int*      scount = (int*)(sh + NMS_W_CNT);

    int b = blockIdx.x, t = threadIdx.x;

    // validity words + scores
    {
        float v = (t < NTOP) ? g_topv[b * NTOP + t] : -1.0f;
        ssv[t] = v;
        unsigned wd = __ballot_sync(0xffffffffu, v >= 0.5f);
        if ((t & 31) == 0) svalid[t >> 5] = wd;
    }

    // warp 0: build ordered list of flagged rows
    if (t < 32) {
        int l = t;
        unsigned flag = g_rowflag[b * 32 + l];
        int c = __popc(flag);
        int pr = c;
#pragma unroll
        for (int off = 1; off < 32; off <<= 1) {
            int n = __shfl_up_sync(0xffffffffu, pr, off);
            if (l >= off) pr += n;
        }
        int base = pr - c;
        int total = __shfl_sync(0xffffffffu, pr, 31);
        unsigned f = flag;
        int p = base;
        while (f) {
            int ii = __ffs(f) - 1; f &= f - 1;
            slist[p++] = l * 32 + ii;   // ascending within lane + lane-ordered base = global order
        }
        if (l == 0) scount[0] = total;
    }
    __syncthreads();

    // stage flagged rows only (padded stride 33, conflict-free)
    int S = scount[0];
    for (int idx = t; idx < S * 32; idx += 1024) {
        int r = idx >> 5, w = idx & 31;
        sst[r * 33 + w] = g_maskbits[((size_t)b * NTOP + slist[r]) * 32 + w];
    }
    __syncthreads();

    // warp 0: serial greedy scan over flagged rows (exact: unflagged rows are no-ops)
    if (t < 32) {
        int l = t;
        unsigned removed_l = 0;
        for (int s = 0; s < S; s++) {
            int i = slist[s];
            unsigned rowword = sst[s * 33 + l];
            int g = i >> 5, ii = i & 31;
            unsigned rw = __shfl_sync(0xffffffffu, removed_l, g);
            bool alive = ((svalid[g] >> ii) & 1u) && !((rw >> ii) & 1u);
            if (alive) removed_l |= rowword;
        }
        srem[l] = removed_l;
    }
    __syncthreads();

    // output
    if (t < NTOP) {
        bool keep = (ssv[t] >= 0.5f) && !((srem[t >> 5] >> (t & 31)) & 1u);
        float fk = keep ? 1.0f : 0.0f;
        int o = b * NTOP + t;
        float4 bb = g_tb[o];
        float4 o0 = make_float4(ssv[t] * fk, bb.x * fk, bb.y * fk, bb.z * fk);
        float4 o1 = make_float4(bb.w * fk, (float)b * fk, g_clsf[o] * fk, 0.0f);
        ((float4*)out)[o * 2 + 0] = o0;
        ((float4*)out)[o * 2 + 1] = o1;
    }
}

// -------------------- launch --------------------
extern "C" void kernel_launch(void* const* d_in, const int* in_sizes, int n_in,
                              void* d_out, int out_size) {
    const float* boxes  = (const float*)d_in[0];
    const float* scores = (const float*)d_in[1];
    if (n_in >= 2 && in_sizes[0] > in_sizes[1]) {
        const float* tmp = boxes; boxes = scores; scores = tmp;
    }
    cudaFuncSetAttribute(k_mega, cudaFuncAttributeMaxDynamicSharedMemorySize,
                         MEGA_SMEM_WORDS * 4);
    cudaFuncSetAttribute(k_nms, cudaFuncAttributeMaxDynamicSharedMemorySize,
                         NMS_SMEM_WORDS * 4);
    k_conf<<<(NB * NA) / 8, 256>>>(scores);
    k_mega<<<NB, 1024, MEGA_SMEM_WORDS * 4>>>(boxes);
    k_iou<<<dim3(NTOP / 8, NB), 256>>>();
    k_nms<<<NB, 1024, NMS_SMEM_WORDS * 4>>>((float*)d_out);
    (void)out_size;
}

// round 5
// speedup vs baseline: 3.5261x; 1.1474x over previous
#include <cuda_runtime.h>
#include <cstdint>

#define NB   8
#define NA   25200
#define NC   80
#define NTOP 1000
#define NBINS 4096
#define CAP  6144
#define NTILE 32     // ceil(NTOP/32)
#define NPAIR 528    // NTILE*(NTILE+1)/2 upper-tri tiles

// -------------------- scratch (device globals; no allocation) --------------------
__device__ unsigned long long g_selkey[NB * NA];   // (bits(1-masked)<<32) | (anchor<<7) | cls
__device__ int                g_hist[NB * NBINS];  // zero at load; k_mega re-zeroes each replay
__device__ float              g_topv[NB * NTOP];
__device__ float              g_clsf[NB * NTOP];
__device__ float4             g_tb[NB * NTOP];
__device__ float4             g_ob[NB * NTOP];
__device__ unsigned           g_maskbits[NB * NTOP * 32]; // lower-tri words stay 0 forever
__device__ unsigned           g_rowflag[NB * 32];

// -------------------- kernel 1: conf/argmax (1 LDG.128/lane + REDUX) + key + histogram --------------------
__global__ __launch_bounds__(256) void k_conf(const float* __restrict__ scores) {
    int gw   = blockIdx.x * 8 + (threadIdx.x >> 5);   // b*NA + a
    int lane = threadIdx.x & 31;
    const float4* s4 = (const float4*)(scores + (size_t)gw * NC);

    unsigned b0 = 0, b1 = 0, b2 = 0, b3 = 0;
    if (lane < 20) {
        float4 v = s4[lane];
        b0 = __float_as_uint(v.x); b1 = __float_as_uint(v.y);
        b2 = __float_as_uint(v.z); b3 = __float_as_uint(v.w);
    }
    unsigned mx = b0 > b1 ? b0 : b1;
    unsigned m2 = b2 > b3 ? b2 : b3;
    if (m2 > mx) mx = m2;
    unsigned wmx = __reduce_max_sync(0xffffffffu, mx);
    unsigned cand = 0xFFu;
    if (b3 == wmx) cand = 4u * lane + 3u;
    if (b2 == wmx) cand = 4u * lane + 2u;
    if (b1 == wmx) cand = 4u * lane + 1u;
    if (b0 == wmx) cand = 4u * lane + 0u;
    cand = __reduce_min_sync(0xffffffffu, cand);   // smallest class among maxima (jnp.argmax)

    if (lane == 0) {
        float conf = __uint_as_float(wmx);
        float m    = (conf >= 0.5f) ? conf : -1.0f;
        float t    = 1.0f - m;                     // exact (Sterbenz) for m in [0.5,1]
        unsigned tb = __float_as_uint(t);
        int b = gw / NA;
        int a = gw - b * NA;
        g_selkey[gw] = ((unsigned long long)tb << 32) | ((unsigned)(a << 7)) | cand;
        atomicAdd(&g_hist[b * NBINS + (tb >> 20)], 1);
    }
}

// -------------------- kernel 2: mega (decide + bin-grouped compact + per-bin rank + gather) --------------------
#define MEGA_W_CAND 0
#define MEGA_W_PRE  12288
#define MEGA_W_CNT  16384
#define MEGA_W_WSUM 20480
#define MEGA_W_SCAL 20512
#define MEGA_SMEM_WORDS 20516
__global__ __launch_bounds__(1024) void k_mega(const float* __restrict__ boxes) {
    extern __shared__ unsigned shm[];
    unsigned long long* cand = (unsigned long long*)(shm + MEGA_W_CAND);
    int* pre  = (int*)(shm + MEGA_W_PRE);
    int* cnt  = (int*)(shm + MEGA_W_CNT);
    int* wsum = (int*)(shm + MEGA_W_WSUM);
    int* scal = (int*)(shm + MEGA_W_SCAL);   // [0]=s_sel [1]=chosen [2]=m

    int b = blockIdx.x, t = threadIdx.x;
    int lane = t & 31, wid = t >> 5;

    if (t < 32) g_rowflag[b * 32 + t] = 0;    // reset for this replay's k_iou

    int hb = b * NBINS + t * 4;
    int h0 = g_hist[hb + 0], h1 = g_hist[hb + 1], h2 = g_hist[hb + 2], h3 = g_hist[hb + 3];
    g_hist[hb + 0] = 0; g_hist[hb + 1] = 0; g_hist[hb + 2] = 0; g_hist[hb + 3] = 0;
    int local = h0 + h1 + h2 + h3;

    int v = local;
#pragma unroll
    for (int off = 1; off < 32; off <<= 1) {
        int n = __shfl_up_sync(0xffffffffu, v, off);
        if (lane >= off) v += n;
    }
    if (lane == 31) wsum[wid] = v;
    if (t == 0) scal[0] = 1024;
    __syncthreads();
    if (t < 32) {
        int s = wsum[t];
        int is = s;
#pragma unroll
        for (int off = 1; off < 32; off <<= 1) {
            int n = __shfl_up_sync(0xffffffffu, is, off);
            if (t >= off) is += n;
        }
        wsum[t] = is - s;
    }
    __syncthreads();
    int incl = v + wsum[wid];
    int excl = incl - local;
    pre[t * 4 + 0] = excl;
    pre[t * 4 + 1] = excl + h0;
    pre[t * 4 + 2] = excl + h0 + h1;
    pre[t * 4 + 3] = excl + h0 + h1 + h2;
    cnt[t * 4 + 0] = 0; cnt[t * 4 + 1] = 0; cnt[t * 4 + 2] = 0; cnt[t * 4 + 3] = 0;
    if (excl < NTOP && incl >= NTOP) atomicMin(&scal[0], t);
    __syncthreads();
    if (t == scal[0]) {
        int bin, mm;
        if      (excl + h0 >= NTOP)           { bin = t * 4 + 0; mm = excl + h0; }
        else if (excl + h0 + h1 >= NTOP)      { bin = t * 4 + 1; mm = excl + h0 + h1; }
        else if (excl + h0 + h1 + h2 >= NTOP) { bin = t * 4 + 2; mm = excl + h0 + h1 + h2; }
        else                                  { bin = t * 4 + 3; mm = excl + local; }
        scal[1] = bin; scal[2] = mm;
    }
    __syncthreads();
    int chosen = scal[1];
    int m = scal[2]; if (m > CAP) m = CAP;

    // bin-grouped compaction, 2 keys per LDG.128 (order within bin irrelevant: rank is order-independent)
    const ulonglong2* keys2 = (const ulonglong2*)(g_selkey + (size_t)b * NA);
    for (int i = t; i < NA / 2; i += 1024) {
        ulonglong2 kk = keys2[i];
        int bin0 = (int)(kk.x >> 52);
        if (bin0 <= chosen) {
            int pos = pre[bin0] + atomicAdd(&cnt[bin0], 1);
            if (pos < CAP) cand[pos] = kk.x;
        }
        int bin1 = (int)(kk.y >> 52);
        if (bin1 <= chosen) {
            int pos = pre[bin1] + atomicAdd(&cnt[bin1], 1);
            if (pos < CAP) cand[pos] = kk.y;
        }
    }
    __syncthreads();

    const float4* bx4 = (const float4*)boxes;
    for (int e = t; e < m; e += 1024) {
        unsigned long long ke = cand[e];
        int bin = (int)(ke >> 52);
        int start = pre[bin];
        int end   = start + cnt[bin]; if (end > m) end = m;
        int rank  = start;
        for (int j = start; j < end; j++) rank += (cand[j] < ke) ? 1 : 0;
        if (rank < NTOP) {
            int a   = (int)((unsigned)(ke & 0xFFFFFFFFull) >> 7);
            int cls = (int)(ke & 127ull);
            float tt = __uint_as_float((unsigned)(ke >> 32));
            float vv = 1.0f - tt;                // bit-exact reconstruction of masked conf
            float cf = (float)cls;
            float4 bb = bx4[b * NA + a];
            int o = b * NTOP + rank;
            g_topv[o] = vv;
            g_clsf[o] = cf;
            g_tb[o]   = bb;
            float off = cf * 4096.0f;
            g_ob[o]   = make_float4(bb.x + off, bb.y + off, bb.z + off, bb.w + off);
        }
    }
}

// -------------------- kernel 3: IoU upper-triangle tiles + zero-inter fast path --------------------
__global__ __launch_bounds__(256) void k_iou() {
    int b = blockIdx.y;
    __shared__ float4 sob[NTILE * 32];     // 1024 entries (pad with zero boxes)
    __shared__ float  sar[NTILE * 32];
    for (int i = threadIdx.x; i < NTILE * 32; i += 256) {
        float4 q = (i < NTOP) ? g_ob[b * NTOP + i] : make_float4(0.f, 0.f, 0.f, 0.f);
        sob[i] = q;
        sar[i] = (q.z - q.x) * (q.w - q.y);
    }
    __syncthreads();

    int w = threadIdx.x >> 5, l = threadIdx.x & 31;
    int s = blockIdx.x * 8 + w;            // tile id in [0, 528)
    // decode upper-triangular (TI, TJ), TJ >= TI
    int TI = 0, rem = s;
    while (rem >= NTILE - TI) { rem -= NTILE - TI; TI++; }
    int TJ = TI + rem;

    int j = TJ * 32 + l;
    float4 bj   = sob[j];
    float areaj = sar[j];
    unsigned myword = 0;

#pragma unroll 1
    for (int ii = 0; ii < 32; ii++) {
        int i = TI * 32 + ii;
        float4 bi = sob[i];                // LDS broadcast
        float xx1 = fmaxf(bi.x, bj.x);
        float yy1 = fmaxf(bi.y, bj.y);
        float xx2 = fminf(bi.z, bj.z);
        float yy2 = fminf(bi.w, bj.w);
        float iw = fmaxf(xx2 - xx1, 0.0f);
        float ih = fmaxf(yy2 - yy1, 0.0f);
        bool candp = (iw > 0.0f) && (ih > 0.0f) && (j > i) && (j < NTOP) && (i < NTOP);
        unsigned any = __ballot_sync(0xffffffffu, candp);
        unsigned word = 0;
        if (any) {                          // warp-uniform: skip division when no intersection
            float inter = iw * ih;
            float u = sar[i] + areaj - inter + 1e-7f;
            bool sup = candp && ((inter / u) > 0.6f);   // exact div: match reference rounding
            word = __ballot_sync(0xffffffffu, sup);
        }
        if (l == ii) myword = word;
    }

    int i_row = TI * 32 + l;
    bool valid_row = (i_row < NTOP);
    if (valid_row) g_maskbits[((size_t)b * NTOP + i_row) * 32 + TJ] = myword;
    unsigned fl = __ballot_sync(0xffffffffu, (myword != 0) && valid_row);
    if (l == 0 && fl) atomicOr(&g_rowflag[b * 32 + TI], fl);
}

// -------------------- kernel 4: sparse greedy scan + output (latency-overlapped) --------------------
// dyn smem (words): sst 1000*33 | slist 1024 | svalid 32 | srem 32 | scount 4
#define NMS_W_SST   0
#define NMS_W_LIST  33000
#define NMS_W_VAL   34024
#define NMS_W_REM   34056
#define NMS_W_CNT   34088
#define NMS_SMEM_WORDS 34092
__global__ __launch_bounds__(1024) void k_nms(float* __restrict__ out) {
    extern __shared__ unsigned sh[];
    unsigned* sst    = sh + NMS_W_SST;
    int*      slist  = (int*)(sh + NMS_W_LIST);
    unsigned* svalid = sh + NMS_W_VAL;
    unsigned* srem   = sh + NMS_W_REM;
    int*      scount = (int*)(sh + NMS_W_CNT);

    int b = blockIdx.x, t = threadIdx.x;

    // independent register loads issue early (overlap list build)
    float  v  = (t < NTOP) ? g_topv[b * NTOP + t] : -1.0f;
    float4 bb = make_float4(0.f, 0.f, 0.f, 0.f);
    float  cf = 0.0f;
    if (t < NTOP) { bb = g_tb[b * NTOP + t]; cf = g_clsf[b * NTOP + t]; }

    unsigned wd = __ballot_sync(0xffffffffu, v >= 0.5f);
    if ((t & 31) == 0) svalid[t >> 5] = wd;

    // warp 0: build ordered list of flagged rows
    if (t < 32) {
        int l = t;
        unsigned flag = g_rowflag[b * 32 + l];
        int c = __popc(flag);
        int pr = c;
#pragma unroll
        for (int off = 1; off < 32; off <<= 1) {
            int n = __shfl_up_sync(0xffffffffu, pr, off);
            if (l >= off) pr += n;
        }
        int base = pr - c;
        int total = __shfl_sync(0xffffffffu, pr, 31);
        unsigned f = flag;
        int p = base;
        while (f) {
            int ii = __ffs(f) - 1; f &= f - 1;
            slist[p++] = l * 32 + ii;
        }
        if (l == 0) scount[0] = total;
    }
    __syncthreads();

    // stage flagged rows (padded stride 33)
    int S = scount[0];
    for (int idx = t; idx < S * 32; idx += 1024) {
        int r = idx >> 5, ww = idx & 31;
        sst[r * 33 + ww] = g_maskbits[((size_t)b * NTOP + slist[r]) * 32 + ww];
    }
    __syncthreads();

    // warp 0: serial greedy scan over flagged rows (exact: unflagged rows are no-ops)
    if (t < 32) {
        int l = t;
        unsigned removed_l = 0;
        for (int s = 0; s < S; s++) {
            int i = slist[s];
            unsigned rowword = sst[s * 33 + l];
            int g = i >> 5, ii = i & 31;
            unsigned rw = __shfl_sync(0xffffffffu, removed_l, g);
            bool alive = ((svalid[g] >> ii) & 1u) && !((rw >> ii) & 1u);
            if (alive) removed_l |= rowword;
        }
        srem[l] = removed_l;
    }
    __syncthreads();

    if (t < NTOP) {
        bool keep = (v >= 0.5f) && !((srem[t >> 5] >> (t & 31)) & 1u);
        float fk = keep ? 1.0f : 0.0f;
        int o = b * NTOP + t;
        float4 o0 = make_float4(v * fk, bb.x * fk, bb.y * fk, bb.z * fk);
        float4 o1 = make_float4(bb.w * fk, (float)b * fk, cf * fk, 0.0f);
        ((float4*)out)[o * 2 + 0] = o0;
        ((float4*)out)[o * 2 + 1] = o1;
    }
}

// -------------------- launch --------------------
extern "C" void kernel_launch(void* const* d_in, const int* in_sizes, int n_in,
                              void* d_out, int out_size) {
    const float* boxes  = (const float*)d_in[0];
    const float* scores = (const float*)d_in[1];
    if (n_in >= 2 && in_sizes[0] > in_sizes[1]) {
        const float* tmp = boxes; boxes = scores; scores = tmp;
    }
    cudaFuncSetAttribute(k_mega, cudaFuncAttributeMaxDynamicSharedMemorySize,
                         MEGA_SMEM_WORDS * 4);
    cudaFuncSetAttribute(k_nms, cudaFuncAttributeMaxDynamicSharedMemorySize,
                         NMS_SMEM_WORDS * 4);
    k_conf<<<(NB * NA) / 8, 256>>>(scores);
    k_mega<<<NB, 1024, MEGA_SMEM_WORDS * 4>>>(boxes);
    k_iou<<<dim3(NPAIR / 8, NB), 256>>>();
    k_nms<<<NB, 1024, NMS_SMEM_WORDS * 4>>>((float*)d_out);
    (void)out_size;
}